// round 3
// baseline (speedup 1.0000x reference)
#include <cuda_runtime.h>

#define NN 16384
#define DEG 20
typedef unsigned long long u64;

__device__ float g_qt[NN * 32];

static __device__ __forceinline__ u64 pk2(float lo, float hi) {
    u64 r; asm("mov.b64 %0, {%1, %2};" : "=l"(r) : "f"(lo), "f"(hi)); return r;
}
static __device__ __forceinline__ void upk2(u64 v, float& lo, float& hi) {
    asm("mov.b64 {%0, %1}, %2;" : "=f"(lo), "=f"(hi) : "l"(v));
}
static __device__ __forceinline__ u64 f2(u64 a, u64 b, u64 c) {
    u64 d; asm("fma.rn.f32x2 %0, %1, %2, %3;" : "=l"(d) : "l"(a), "l"(b), "l"(c)); return d;
}
static __device__ __forceinline__ float ss(float x) {
    return x > 0.f ? __expf(__fdividef(-1.f, x)) : 0.f;
}
static __device__ __forceinline__ float bsum(float v) {
#pragma unroll
    for (int o = 16; o >= 1; o >>= 1) v += __shfl_xor_sync(0xffffffffu, v, o);
    return v;
}

// ---------------- K0: fold Wq@Wd/sqrt(8) into per-node query ----------------
__global__ void k0_qt(const float* __restrict__ f, const float* __restrict__ Wq_s,
                      const float* __restrict__ Wq_v, const float* __restrict__ Wd_s,
                      const float* __restrict__ Wd_v) {
    __shared__ float As[64], Av[64];
    int t = threadIdx.x;
    if (t < 64) {
        int m = t >> 3, j = t & 7;
        float s = 0.f, v = 0.f;
#pragma unroll
        for (int o = 0; o < 8; o++) {
            s = fmaf(Wq_s[m * 8 + o], Wd_s[o * 8 + j], s);
            v = fmaf(Wq_v[m * 8 + o], Wd_v[o * 8 + j], v);
        }
        As[t] = s * 0.35355339059327373f;
        Av[t] = v * 0.35355339059327373f;
    }
    __syncthreads();
    int n = blockIdx.x * 256 + t;
    float fs[8], fv[24];
#pragma unroll
    for (int m = 0; m < 8; m++) fs[m] = f[n * 32 + m];
#pragma unroll
    for (int m = 0; m < 24; m++) fv[m] = f[n * 32 + 8 + m];
#pragma unroll
    for (int j = 0; j < 8; j++) {
        float s = 0.f;
#pragma unroll
        for (int m = 0; m < 8; m++) s = fmaf(fs[m], As[m * 8 + j], s);
        g_qt[n * 32 + j] = s;
    }
#pragma unroll
    for (int j = 0; j < 8; j++) {
        float v0 = 0.f, v1 = 0.f, v2 = 0.f;
#pragma unroll
        for (int m = 0; m < 8; m++) {
            float a = Av[m * 8 + j];
            v0 = fmaf(fv[m * 3 + 0], a, v0);
            v1 = fmaf(fv[m * 3 + 1], a, v1);
            v2 = fmaf(fv[m * 3 + 2], a, v2);
        }
        g_qt[n * 32 + 8 + j * 3 + 0] = v0;
        g_qt[n * 32 + 8 + j * 3 + 1] = v1;
        g_qt[n * 32 + 8 + j * 3 + 2] = v2;
    }
}

// ---------------- main: 4 warps per node, warp = one tp path ----------------
#define SM_W2K 0
#define SM_W2V 16384
#define SM_W1K 32768
#define SM_W1V 33408
#define SM_NS  34048
#define NS_STR 2560
#define NS_H   0      // [64][20]
#define NS_GS  1280   // [20][8]
#define NS_GD  1440   // [20][8]
#define NS_GV  1600   // [20][8][3]
#define NS_U   2080   // [20][3]
#define NS_EMB 2140   // [20][10]
#define NS_LC  2340   // [20]
#define NS_LP  2360   // [4][20]
#define NS_CO  2440   // [20]
#define NS_OS  2460   // [2][8]
#define NS_OV  2476   // [2][24]
#define SMEM_BYTES ((SM_NS + 4 * NS_STR) * 4)

__global__ __launch_bounds__(512, 1) void se3_main(
    const float* __restrict__ f, const float* __restrict__ pos,
    const float* __restrict__ Wk1, const float* __restrict__ Wk2,
    const float* __restrict__ Wv1, const float* __restrict__ Wv2,
    const int* __restrict__ edge_src, float* __restrict__ out) {
    extern __shared__ float sm[];
    const int tid = threadIdx.x;
    const int wid = tid >> 5, lane = tid & 31;

    // stage weights
    {
        float4* s4 = (float4*)sm;
        for (int i = tid; i < 4096; i += 512) {
            s4[i] = ((const float4*)Wk2)[i];
            s4[4096 + i] = ((const float4*)Wv2)[i];
        }
        for (int i = tid; i < 160; i += 512) {
            s4[8192 + i] = ((const float4*)Wk1)[i];
            s4[8352 + i] = ((const float4*)Wv1)[i];
        }
    }

    const int nl = wid >> 2, q = wid & 3;
    const int n = blockIdx.x * 4 + nl;
    float* ns = sm + SM_NS + nl * NS_STR;
    const int i0 = lane >> 3, oo = lane & 7;  // out0=(i0,oo), out1=(i0+4,oo)

    // ---- edge setup: warp q handles edges q*5 .. q*5+4 ----
    {
        const float px = pos[n * 3 + 0], py = pos[n * 3 + 1], pz = pos[n * 3 + 2];
#pragma unroll
        for (int k = 0; k < 5; k++) {
            int e = q * 5 + k;
            int src = edge_src[n * DEG + e];
            float dx = pos[src * 3 + 0] - px;
            float dy = pos[src * 3 + 1] - py;
            float dz = pos[src * 3 + 2] - pz;
            float r2 = fmaf(dx, dx, fmaf(dy, dy, dz * dz));
            float ir = rsqrtf(r2);
            float r = r2 * ir;
            float u0 = dx * ir, u1 = dy * ir, u2 = dz * ir;
            if (lane < 8) {
                int i = lane;
                float gsv = f[src * 32 + i];
                float a0 = f[src * 32 + 8 + 3 * i + 0];
                float a1 = f[src * 32 + 8 + 3 * i + 1];
                float a2 = f[src * 32 + 8 + 3 * i + 2];
                ns[NS_GS + e * 8 + i] = gsv;
                ns[NS_GV + e * 24 + i * 3 + 0] = a0;
                ns[NS_GV + e * 24 + i * 3 + 1] = a1;
                ns[NS_GV + e * 24 + i * 3 + 2] = a2;
                ns[NS_GD + e * 8 + i] = fmaf(a0, u0, fmaf(a1, u1, a2 * u2));
            } else if (lane < 18) {
                int b = lane - 8;
                float rr = r * (11.0f / 3.5f);
                float d = rr - (float)(b + 1);
                ns[NS_EMB + e * 10 + b] = 26.66929f * ss(d + 1.f) * ss(1.f - d);
            } else if (lane == 18) {
                ns[NS_U + e * 3 + 0] = u0;
                ns[NS_U + e * 3 + 1] = u1;
                ns[NS_U + e * 3 + 2] = u2;
                float x = 10.f * (1.f - r * (1.f / 3.5f));
                ns[NS_LC + e] = (x > 0.f) ? -__fdividef(1.f, x) : -1e30f;
            }
        }
    }
    __syncthreads();

    // lane's query slice
    const float qso = g_qt[n * 32 + oo];
    const float qv0 = g_qt[n * 32 + 8 + oo * 3 + 0];
    const float qv1 = g_qt[n * 32 + 8 + oo * 3 + 1];
    const float qv2 = g_qt[n * 32 + 8 + oo * 3 + 2];

    float vs = 0.f, vv0 = 0.f, vv1 = 0.f, vv2 = 0.f;

#pragma unroll 1
    for (int pass = 0; pass < 2; pass++) {
        const float* W1 = sm + (pass ? SM_W1V : SM_W1K);
        const float* W2 = sm + (pass ? SM_W2V : SM_W2K);

        // ---- FC1: warp q computes t in [16q, 16q+16), lane = edge ----
        if (lane < 20) {
            float em[10];
#pragma unroll
            for (int b = 0; b < 10; b++) em[b] = ns[NS_EMB + lane * 10 + b];
#pragma unroll
            for (int tt = 0; tt < 16; tt++) {
                int t = q * 16 + tt;
                float a = 0.f;
#pragma unroll
                for (int b = 0; b < 10; b++) a = fmaf(em[b], W1[b * 64 + t], a);
                a *= 0.31622776601683794f;
                float h = __fdividef(a, 1.f + __expf(-a));
                ns[NS_H + t * 20 + lane] = h * 0.125f;  // folds FC2 /sqrt(64)
            }
        }
        __syncthreads();

        // ---- FC2: edges packed in f32x2 lanes, weights duplicated ----
        u64 acc0[10], acc1[10];
#pragma unroll
        for (int e = 0; e < 10; e++) { acc0[e] = 0ULL; acc1[e] = 0ULL; }
        {
            const float* wp = W2 + q * 64 + lane;
#pragma unroll 8
            for (int t = 0; t < 64; t++) {
                float w0 = wp[t * 256];
                float w1 = wp[t * 256 + 32];
                u64 wd0 = pk2(w0, w0), wd1 = pk2(w1, w1);
                const ulonglong2* hp = (const ulonglong2*)(ns + NS_H + t * 20);
                ulonglong2 hA = hp[0], hB = hp[1], hC = hp[2], hD = hp[3], hE = hp[4];
                acc0[0] = f2(wd0, hA.x, acc0[0]); acc1[0] = f2(wd1, hA.x, acc1[0]);
                acc0[1] = f2(wd0, hA.y, acc0[1]); acc1[1] = f2(wd1, hA.y, acc1[1]);
                acc0[2] = f2(wd0, hB.x, acc0[2]); acc1[2] = f2(wd1, hB.x, acc1[2]);
                acc0[3] = f2(wd0, hB.y, acc0[3]); acc1[3] = f2(wd1, hB.y, acc1[3]);
                acc0[4] = f2(wd0, hC.x, acc0[4]); acc1[4] = f2(wd1, hC.x, acc1[4]);
                acc0[5] = f2(wd0, hC.y, acc0[5]); acc1[5] = f2(wd1, hC.y, acc1[5]);
                acc0[6] = f2(wd0, hD.x, acc0[6]); acc1[6] = f2(wd1, hD.x, acc1[6]);
                acc0[7] = f2(wd0, hD.y, acc0[7]); acc1[7] = f2(wd1, hD.y, acc1[7]);
                acc0[8] = f2(wd0, hE.x, acc0[8]); acc1[8] = f2(wd1, hE.x, acc1[8]);
                acc0[9] = f2(wd0, hE.y, acc0[9]); acc1[9] = f2(wd1, hE.y, acc1[9]);
            }
        }

        if (pass == 0) {
            // ---- logits: per-path partial, butterfly per edge ----
            float mine = 0.f;
            if (q < 2) {
                const float* Ab = ns + (q ? NS_GD : NS_GS);
#pragma unroll
                for (int ep = 0; ep < 10; ep++) {
                    float ka0, ka1, kb0, kb1;
                    upk2(acc0[ep], ka0, ka1); upk2(acc1[ep], kb0, kb1);
                    int e0 = 2 * ep, e1 = e0 + 1;
                    float p0 = fmaf(Ab[e0 * 8 + i0], ka0, Ab[e0 * 8 + i0 + 4] * kb0) * qso;
                    float p1 = fmaf(Ab[e1 * 8 + i0], ka1, Ab[e1 * 8 + i0 + 4] * kb1) * qso;
                    p0 = bsum(p0); p1 = bsum(p1);
                    if (lane == e0) mine = p0;
                    if (lane == e1) mine = p1;
                }
            } else if (q == 2) {
#pragma unroll
                for (int ep = 0; ep < 10; ep++) {
                    float ka0, ka1, kb0, kb1;
                    upk2(acc0[ep], ka0, ka1); upk2(acc1[ep], kb0, kb1);
                    int e0 = 2 * ep, e1 = e0 + 1;
                    float B0 = fmaf(qv0, ns[NS_U + e0 * 3 + 0],
                               fmaf(qv1, ns[NS_U + e0 * 3 + 1], qv2 * ns[NS_U + e0 * 3 + 2]));
                    float B1 = fmaf(qv0, ns[NS_U + e1 * 3 + 0],
                               fmaf(qv1, ns[NS_U + e1 * 3 + 1], qv2 * ns[NS_U + e1 * 3 + 2]));
                    float p0 = fmaf(ns[NS_GS + e0 * 8 + i0], ka0,
                                    ns[NS_GS + e0 * 8 + i0 + 4] * kb0) * B0;
                    float p1 = fmaf(ns[NS_GS + e1 * 8 + i0], ka1,
                                    ns[NS_GS + e1 * 8 + i0 + 4] * kb1) * B1;
                    p0 = bsum(p0); p1 = bsum(p1);
                    if (lane == e0) mine = p0;
                    if (lane == e1) mine = p1;
                }
            } else {
#pragma unroll
                for (int ep = 0; ep < 10; ep++) {
                    float ka0, ka1, kb0, kb1;
                    upk2(acc0[ep], ka0, ka1); upk2(acc1[ep], kb0, kb1);
                    int e0 = 2 * ep, e1 = e0 + 1;
                    const float* g0 = ns + NS_GV + e0 * 24;
                    const float* g1 = ns + NS_GV + e1 * 24;
                    float d00 = fmaf(qv0, g0[i0 * 3], fmaf(qv1, g0[i0 * 3 + 1], qv2 * g0[i0 * 3 + 2]));
                    float d01 = fmaf(qv0, g0[(i0 + 4) * 3], fmaf(qv1, g0[(i0 + 4) * 3 + 1], qv2 * g0[(i0 + 4) * 3 + 2]));
                    float d10 = fmaf(qv0, g1[i0 * 3], fmaf(qv1, g1[i0 * 3 + 1], qv2 * g1[i0 * 3 + 2]));
                    float d11 = fmaf(qv0, g1[(i0 + 4) * 3], fmaf(qv1, g1[(i0 + 4) * 3 + 1], qv2 * g1[(i0 + 4) * 3 + 2]));
                    float p0 = fmaf(d00, ka0, d01 * kb0) * 0.5773502691896258f;
                    float p1 = fmaf(d10, ka1, d11 * kb1) * 0.5773502691896258f;
                    p0 = bsum(p0); p1 = bsum(p1);
                    if (lane == e0) mine = p0;
                    if (lane == e1) mine = p1;
                }
            }
            if (lane < 20) ns[NS_LP + q * 20 + lane] = mine;
        } else {
            // ---- v-side accumulation ----
            if (q < 2) {
                const float* Ab = ns + (q ? NS_GD : NS_GS);
#pragma unroll
                for (int ep = 0; ep < 10; ep++) {
                    float ka0, ka1, kb0, kb1;
                    upk2(acc0[ep], ka0, ka1); upk2(acc1[ep], kb0, kb1);
                    int e0 = 2 * ep, e1 = e0 + 1;
                    float c0 = ns[NS_CO + e0], c1 = ns[NS_CO + e1];
                    vs = fmaf(c0 * Ab[e0 * 8 + i0], ka0, vs);
                    vs = fmaf(c0 * Ab[e0 * 8 + i0 + 4], kb0, vs);
                    vs = fmaf(c1 * Ab[e1 * 8 + i0], ka1, vs);
                    vs = fmaf(c1 * Ab[e1 * 8 + i0 + 4], kb1, vs);
                }
            } else if (q == 2) {
#pragma unroll
                for (int ep = 0; ep < 10; ep++) {
                    float ka0, ka1, kb0, kb1;
                    upk2(acc0[ep], ka0, ka1); upk2(acc1[ep], kb0, kb1);
                    int e0 = 2 * ep, e1 = e0 + 1;
                    float c0 = ns[NS_CO + e0], c1 = ns[NS_CO + e1];
                    float s0 = c0 * 1.7320508075688772f *
                               fmaf(ns[NS_GS + e0 * 8 + i0], ka0, ns[NS_GS + e0 * 8 + i0 + 4] * kb0);
                    float s1 = c1 * 1.7320508075688772f *
                               fmaf(ns[NS_GS + e1 * 8 + i0], ka1, ns[NS_GS + e1 * 8 + i0 + 4] * kb1);
                    vv0 = fmaf(s0, ns[NS_U + e0 * 3 + 0], vv0);
                    vv1 = fmaf(s0, ns[NS_U + e0 * 3 + 1], vv1);
                    vv2 = fmaf(s0, ns[NS_U + e0 * 3 + 2], vv2);
                    vv0 = fmaf(s1, ns[NS_U + e1 * 3 + 0], vv0);
                    vv1 = fmaf(s1, ns[NS_U + e1 * 3 + 1], vv1);
                    vv2 = fmaf(s1, ns[NS_U + e1 * 3 + 2], vv2);
                }
            } else {
#pragma unroll
                for (int ep = 0; ep < 10; ep++) {
                    float ka0, ka1, kb0, kb1;
                    upk2(acc0[ep], ka0, ka1); upk2(acc1[ep], kb0, kb1);
                    int e0 = 2 * ep, e1 = e0 + 1;
                    float c0 = ns[NS_CO + e0], c1 = ns[NS_CO + e1];
                    const float* g0 = ns + NS_GV + e0 * 24;
                    const float* g1 = ns + NS_GV + e1 * 24;
                    float a0 = c0 * ka0, b0 = c0 * kb0;
                    float a1 = c1 * ka1, b1 = c1 * kb1;
                    vv0 = fmaf(a0, g0[i0 * 3 + 0], fmaf(b0, g0[(i0 + 4) * 3 + 0], vv0));
                    vv1 = fmaf(a0, g0[i0 * 3 + 1], fmaf(b0, g0[(i0 + 4) * 3 + 1], vv1));
                    vv2 = fmaf(a0, g0[i0 * 3 + 2], fmaf(b0, g0[(i0 + 4) * 3 + 2], vv2));
                    vv0 = fmaf(a1, g1[i0 * 3 + 0], fmaf(b1, g1[(i0 + 4) * 3 + 0], vv0));
                    vv1 = fmaf(a1, g1[i0 * 3 + 1], fmaf(b1, g1[(i0 + 4) * 3 + 1], vv1));
                    vv2 = fmaf(a1, g1[i0 * 3 + 2], fmaf(b1, g1[(i0 + 4) * 3 + 2], vv2));
                }
            }
        }
        __syncthreads();

        if (pass == 0 && q == 0) {
            // softmax over 20 edges (node's warp 0); coef includes 0.25 tp norm
            float L = -3.0e38f;
            if (lane < 20)
                L = fmaf(0.022097086912079608f,
                         ns[NS_LP + lane] + ns[NS_LP + 20 + lane] +
                             ns[NS_LP + 40 + lane] + ns[NS_LP + 60 + lane],
                         ns[NS_LC + lane]);
            float M = L;
#pragma unroll
            for (int o = 16; o >= 1; o >>= 1)
                M = fmaxf(M, __shfl_xor_sync(0xffffffffu, M, o));
            float ex = (lane < 20) ? __expf(L - M) : 0.f;
            float z = bsum(ex);
            if (lane < 20) ns[NS_CO + lane] = 0.25f * sqrtf(__fdividef(ex, z) + 1e-12f);
        }
        // coef write is ordered before pass-1 reads by the post-FC1 __syncthreads
    }

    // ---- reduce over i-groups (xor 16, 8) and combine across warps ----
    if (q < 2) {
#pragma unroll
        for (int o = 16; o >= 8; o >>= 1) vs += __shfl_xor_sync(0xffffffffu, vs, o);
        if (lane < 8) ns[NS_OS + q * 8 + lane] = vs;
    } else {
#pragma unroll
        for (int o = 16; o >= 8; o >>= 1) {
            vv0 += __shfl_xor_sync(0xffffffffu, vv0, o);
            vv1 += __shfl_xor_sync(0xffffffffu, vv1, o);
            vv2 += __shfl_xor_sync(0xffffffffu, vv2, o);
        }
        if (lane < 8) {
            ns[NS_OV + (q - 2) * 24 + lane * 3 + 0] = vv0;
            ns[NS_OV + (q - 2) * 24 + lane * 3 + 1] = vv1;
            ns[NS_OV + (q - 2) * 24 + lane * 3 + 2] = vv2;
        }
    }
    __syncthreads();
    if (q == 0) {
        if (lane < 8) out[n * 32 + lane] = ns[NS_OS + lane] + ns[NS_OS + 8 + lane];
        int idx = lane - 8;
        if (idx >= 0) out[n * 32 + 8 + idx] = ns[NS_OV + idx] + ns[NS_OV + 24 + idx];
    }
}

extern "C" void kernel_launch(void* const* d_in, const int* in_sizes, int n_in,
                              void* d_out, int out_size) {
    const float* f    = (const float*)d_in[0];
    const float* pos  = (const float*)d_in[1];
    const float* Wq_s = (const float*)d_in[2];
    const float* Wq_v = (const float*)d_in[3];
    const float* Wk1  = (const float*)d_in[4];
    const float* Wk2  = (const float*)d_in[5];
    const float* Wv1  = (const float*)d_in[6];
    const float* Wv2  = (const float*)d_in[7];
    const float* Wd_s = (const float*)d_in[8];
    const float* Wd_v = (const float*)d_in[9];
    const int* esrc   = (const int*)d_in[10];
    float* out = (float*)d_out;

    cudaFuncSetAttribute(se3_main, cudaFuncAttributeMaxDynamicSharedMemorySize, SMEM_BYTES);
    k0_qt<<<64, 256>>>(f, Wq_s, Wq_v, Wd_s, Wd_v);
    se3_main<<<4096, 512, SMEM_BYTES>>>(f, pos, Wk1, Wk2, Wv1, Wv2, esrc, out);
}

// round 4
// speedup vs baseline: 1.2373x; 1.2373x over previous
#include <cuda_runtime.h>

#define NN 16384
#define DEG 20
typedef unsigned long long u64;

__device__ float g_qt[NN * 32];

static __device__ __forceinline__ u64 pk2(float lo, float hi) {
    u64 r; asm("mov.b64 %0, {%1, %2};" : "=l"(r) : "f"(lo), "f"(hi)); return r;
}
static __device__ __forceinline__ void upk2(u64 v, float& lo, float& hi) {
    asm("mov.b64 {%0, %1}, %2;" : "=f"(lo), "=f"(hi) : "l"(v));
}
static __device__ __forceinline__ u64 f2(u64 a, u64 b, u64 c) {
    u64 d; asm("fma.rn.f32x2 %0, %1, %2, %3;" : "=l"(d) : "l"(a), "l"(b), "l"(c)); return d;
}
static __device__ __forceinline__ float ss(float x) {
    return x > 0.f ? __expf(__fdividef(-1.f, x)) : 0.f;
}
static __device__ __forceinline__ float bsum(float v) {
#pragma unroll
    for (int o = 16; o >= 1; o >>= 1) v += __shfl_xor_sync(0xffffffffu, v, o);
    return v;
}

// ---------------- K0: fold Wq@Wd/sqrt(8) into per-node query ----------------
__global__ void k0_qt(const float* __restrict__ f, const float* __restrict__ Wq_s,
                      const float* __restrict__ Wq_v, const float* __restrict__ Wd_s,
                      const float* __restrict__ Wd_v) {
    __shared__ float As[64], Av[64];
    int t = threadIdx.x;
    if (t < 64) {
        int m = t >> 3, j = t & 7;
        float s = 0.f, v = 0.f;
#pragma unroll
        for (int o = 0; o < 8; o++) {
            s = fmaf(Wq_s[m * 8 + o], Wd_s[o * 8 + j], s);
            v = fmaf(Wq_v[m * 8 + o], Wd_v[o * 8 + j], v);
        }
        As[t] = s * 0.35355339059327373f;
        Av[t] = v * 0.35355339059327373f;
    }
    __syncthreads();
    int n = blockIdx.x * 256 + t;
    float fs[8], fv[24];
#pragma unroll
    for (int m = 0; m < 8; m++) fs[m] = f[n * 32 + m];
#pragma unroll
    for (int m = 0; m < 24; m++) fv[m] = f[n * 32 + 8 + m];
#pragma unroll
    for (int j = 0; j < 8; j++) {
        float s = 0.f;
#pragma unroll
        for (int m = 0; m < 8; m++) s = fmaf(fs[m], As[m * 8 + j], s);
        g_qt[n * 32 + j] = s;
    }
#pragma unroll
    for (int j = 0; j < 8; j++) {
        float v0 = 0.f, v1 = 0.f, v2 = 0.f;
#pragma unroll
        for (int m = 0; m < 8; m++) {
            float a = Av[m * 8 + j];
            v0 = fmaf(fv[m * 3 + 0], a, v0);
            v1 = fmaf(fv[m * 3 + 1], a, v1);
            v2 = fmaf(fv[m * 3 + 2], a, v2);
        }
        g_qt[n * 32 + 8 + j * 3 + 0] = v0;
        g_qt[n * 32 + 8 + j * 3 + 1] = v1;
        g_qt[n * 32 + 8 + j * 3 + 2] = v2;
    }
}

// ---------------- main: 1 warp per node, 10-edge FC2 sweeps ----------------
// smem: W2[16384] W1[640] then 12 warp-scratch regions of 1920 floats
#define SM_W1 16384
#define SM_NS 17024
#define NS_STR 1920
#define NS_H   0      // [64][12]  (current sweep's h, e-local 0..9)
#define NS_GS  768    // [20][8]
#define NS_GD  928    // [20][8]
#define NS_GV  1088   // [20][8][3]
#define NS_U   1568   // [20][3]
#define NS_EMB 1632   // [20][10]
#define NS_LC  1832   // [20]
#define NS_LG  1856   // [20]
#define NS_CO  1880   // [20]
#define SMEM_BYTES ((SM_NS + 12 * NS_STR) * 4)

static __device__ __forceinline__ void stage(float* sm, const float* W2,
                                             const float* W1, int tid) {
    float4* d = (float4*)sm;
    const float4* s2 = (const float4*)W2;
    const float4* s1 = (const float4*)W1;
    for (int i = tid; i < 4096; i += 384) d[i] = s2[i];
    for (int i = tid; i < 160; i += 384) d[4096 + i] = s1[i];
}

__global__ __launch_bounds__(384, 1) void se3_main(
    const float* __restrict__ f, const float* __restrict__ pos,
    const float* __restrict__ Wk1, const float* __restrict__ Wk2,
    const float* __restrict__ Wv1, const float* __restrict__ Wv2,
    const int* __restrict__ edge_src, float* __restrict__ out) {
    extern __shared__ float sm[];
    const int tid = threadIdx.x;
    const int wid = tid >> 5, lane = tid & 31;
    const int n = blockIdx.x * 12 + wid;
    const bool active = (n < NN);
    float* ws = sm + SM_NS + wid * NS_STR;

    // ---- edge setup: one warp = all 20 edges of its node ----
    if (active) {
        const float px = pos[n * 3 + 0], py = pos[n * 3 + 1], pz = pos[n * 3 + 2];
#pragma unroll 4
        for (int e = 0; e < 20; e++) {
            int src = edge_src[n * DEG + e];
            float dx = pos[src * 3 + 0] - px;
            float dy = pos[src * 3 + 1] - py;
            float dz = pos[src * 3 + 2] - pz;
            float r2 = fmaf(dx, dx, fmaf(dy, dy, dz * dz));
            float ir = rsqrtf(r2);
            float r = r2 * ir;
            float u0 = dx * ir, u1 = dy * ir, u2 = dz * ir;
            if (lane < 8) {
                int i = lane;
                float gsv = f[src * 32 + i];
                float a0 = f[src * 32 + 8 + 3 * i + 0];
                float a1 = f[src * 32 + 8 + 3 * i + 1];
                float a2 = f[src * 32 + 8 + 3 * i + 2];
                ws[NS_GS + e * 8 + i] = gsv;
                ws[NS_GV + e * 24 + i * 3 + 0] = a0;
                ws[NS_GV + e * 24 + i * 3 + 1] = a1;
                ws[NS_GV + e * 24 + i * 3 + 2] = a2;
                ws[NS_GD + e * 8 + i] = fmaf(a0, u0, fmaf(a1, u1, a2 * u2));
            } else if (lane < 18) {
                int b = lane - 8;
                float rr = r * (11.0f / 3.5f);
                float d = rr - (float)(b + 1);
                ws[NS_EMB + e * 10 + b] = 26.66929f * ss(d + 1.f) * ss(1.f - d);
            } else if (lane == 18) {
                ws[NS_U + e * 3 + 0] = u0;
                ws[NS_U + e * 3 + 1] = u1;
                ws[NS_U + e * 3 + 2] = u2;
                float x = 10.f * (1.f - r * (1.f / 3.5f));
                ws[NS_LC + e] = (x > 0.f) ? -__fdividef(1.f, x) : -1e30f;
            }
        }
    }
    stage(sm, Wk2, Wk1, tid);
    __syncthreads();

    const int pr = lane >> 4, ii = (lane >> 1) & 7, jh = lane & 1;
    float qts[4], qtv[4][3];
    if (active) {
#pragma unroll
        for (int k = 0; k < 4; k++) {
            qts[k] = g_qt[n * 32 + jh * 4 + k];
#pragma unroll
            for (int c = 0; c < 3; c++)
                qtv[k][c] = g_qt[n * 32 + 8 + (jh * 4 + k) * 3 + c];
        }
    }

    float outs[4] = {0.f, 0.f, 0.f, 0.f};
    float outv[4][3] = {};

#pragma unroll 1
    for (int pass = 0; pass < 2; pass++) {
        if (pass == 1) {
            __syncthreads();
            stage(sm, Wv2, Wv1, tid);
            __syncthreads();
        }
        if (active) {
#pragma unroll 1
            for (int s = 0; s < 2; s++) {
                // ---- FC1: lane computes t = lane, lane+32 for this sweep ----
                {
                    const float* W1s = sm + SM_W1;
                    float wc0[10], wc1[10];
#pragma unroll
                    for (int b = 0; b < 10; b++) {
                        wc0[b] = W1s[b * 64 + lane];
                        wc1[b] = W1s[b * 64 + 32 + lane];
                    }
#pragma unroll
                    for (int el = 0; el < 10; el++) {
                        int e = s * 10 + el;
                        float a0 = 0.f, a1 = 0.f;
#pragma unroll
                        for (int b = 0; b < 10; b++) {
                            float em = ws[NS_EMB + e * 10 + b];
                            a0 = fmaf(em, wc0[b], a0);
                            a1 = fmaf(em, wc1[b], a1);
                        }
                        a0 *= 0.31622776601683794f;
                        a1 *= 0.31622776601683794f;
                        ws[NS_H + lane * 12 + el] =
                            __fdividef(a0, 1.f + __expf(-a0)) * 0.125f;
                        ws[NS_H + (lane + 32) * 12 + el] =
                            __fdividef(a1, 1.f + __expf(-a1)) * 0.125f;
                    }
                }
                __syncwarp();

                // ---- FC2: 10 edges, edge-packed f32x2; lane owns 8 flat outs ----
                u64 accA[4][5], accB[4][5];
#pragma unroll
                for (int k = 0; k < 4; k++)
#pragma unroll
                    for (int p = 0; p < 5; p++) { accA[k][p] = 0ULL; accB[k][p] = 0ULL; }
                {
                    const float4* w4 = (const float4*)sm;
                    const float* hb = ws + NS_H;
#pragma unroll 4
                    for (int t = 0; t < 64; t++) {
                        float4 wA = w4[t * 64 + lane];
                        float4 wB = w4[t * 64 + 32 + lane];
                        ulonglong2 h01 = *(const ulonglong2*)(hb + t * 12);
                        ulonglong2 h23 = *(const ulonglong2*)(hb + t * 12 + 4);
                        u64 h4 = *(const u64*)(hb + t * 12 + 8);
                        u64 wa[4] = {pk2(wA.x, wA.x), pk2(wA.y, wA.y),
                                     pk2(wA.z, wA.z), pk2(wA.w, wA.w)};
                        u64 wb[4] = {pk2(wB.x, wB.x), pk2(wB.y, wB.y),
                                     pk2(wB.z, wB.z), pk2(wB.w, wB.w)};
                        u64 hh[5] = {h01.x, h01.y, h23.x, h23.y, h4};
#pragma unroll
                        for (int k = 0; k < 4; k++)
#pragma unroll
                            for (int p = 0; p < 5; p++) {
                                accA[k][p] = f2(wa[k], hh[p], accA[k][p]);
                                accB[k][p] = f2(wb[k], hh[p], accB[k][p]);
                            }
                    }
                }

                if (pass == 0) {
                    // ---- logits ----
                    float mine = 0.f;
#pragma unroll
                    for (int p = 0; p < 5; p++) {
                        float vA0[4], vA1[4], vB0[4], vB1[4];
#pragma unroll
                        for (int k = 0; k < 4; k++) {
                            upk2(accA[k][p], vA0[k], vA1[k]);
                            upk2(accB[k][p], vB0[k], vB1[k]);
                        }
                        int e0 = s * 10 + 2 * p, e1 = e0 + 1;
                        float part0, part1;
#pragma unroll
                        for (int h = 0; h < 2; h++) {
                            int e = h ? e1 : e0;
                            float* vA = h ? vA1 : vA0;
                            float* vB = h ? vB1 : vB0;
                            float gse = ws[NS_GS + e * 8 + ii];
                            float sA = pr ? ws[NS_GD + e * 8 + ii] : gse;
                            float dA = fmaf(vA[0], qts[0], fmaf(vA[1], qts[1],
                                        fmaf(vA[2], qts[2], vA[3] * qts[3])));
                            float part = sA * dA;
                            if (pr == 0) {
                                float u0 = ws[NS_U + e * 3 + 0];
                                float u1 = ws[NS_U + e * 3 + 1];
                                float u2 = ws[NS_U + e * 3 + 2];
                                float sum = 0.f;
#pragma unroll
                                for (int k = 0; k < 4; k++) {
                                    float qdu = fmaf(qtv[k][0], u0,
                                                fmaf(qtv[k][1], u1, qtv[k][2] * u2));
                                    sum = fmaf(qdu, vB[k], sum);
                                }
                                part = fmaf(gse, sum, part);
                            } else {
                                float g0 = ws[NS_GV + e * 24 + ii * 3 + 0];
                                float g1 = ws[NS_GV + e * 24 + ii * 3 + 1];
                                float g2 = ws[NS_GV + e * 24 + ii * 3 + 2];
                                float sum = 0.f;
#pragma unroll
                                for (int k = 0; k < 4; k++) {
                                    float cc = fmaf(qtv[k][0], g0,
                                               fmaf(qtv[k][1], g1, qtv[k][2] * g2));
                                    sum = fmaf(cc, vB[k], sum);
                                }
                                part = fmaf(0.5773502691896258f, sum, part);
                            }
                            if (h) part1 = part; else part0 = part;
                        }
                        part0 = bsum(part0);
                        part1 = bsum(part1);
                        if (lane == 2 * p) mine = part0;
                        if (lane == 2 * p + 1) mine = part1;
                    }
                    if (lane < 10) ws[NS_LG + s * 10 + lane] = mine;
                } else {
                    // ---- v-side accumulation ----
#pragma unroll
                    for (int p = 0; p < 5; p++) {
                        float vA0[4], vA1[4], vB0[4], vB1[4];
#pragma unroll
                        for (int k = 0; k < 4; k++) {
                            upk2(accA[k][p], vA0[k], vA1[k]);
                            upk2(accB[k][p], vB0[k], vB1[k]);
                        }
                        int e0 = s * 10 + 2 * p, e1 = e0 + 1;
#pragma unroll
                        for (int h = 0; h < 2; h++) {
                            int e = h ? e1 : e0;
                            float* vA = h ? vA1 : vA0;
                            float* vB = h ? vB1 : vB0;
                            float c = ws[NS_CO + e];
                            float gse = ws[NS_GS + e * 8 + ii];
                            float sA = c * (pr ? ws[NS_GD + e * 8 + ii] : gse);
#pragma unroll
                            for (int k = 0; k < 4; k++) outs[k] = fmaf(sA, vA[k], outs[k]);
                            if (pr == 0) {
                                float b0 = c * 1.7320508075688772f * gse;
                                float t0 = b0 * ws[NS_U + e * 3 + 0];
                                float t1 = b0 * ws[NS_U + e * 3 + 1];
                                float t2 = b0 * ws[NS_U + e * 3 + 2];
#pragma unroll
                                for (int k = 0; k < 4; k++) {
                                    outv[k][0] = fmaf(t0, vB[k], outv[k][0]);
                                    outv[k][1] = fmaf(t1, vB[k], outv[k][1]);
                                    outv[k][2] = fmaf(t2, vB[k], outv[k][2]);
                                }
                            } else {
                                float g0 = c * ws[NS_GV + e * 24 + ii * 3 + 0];
                                float g1 = c * ws[NS_GV + e * 24 + ii * 3 + 1];
                                float g2 = c * ws[NS_GV + e * 24 + ii * 3 + 2];
#pragma unroll
                                for (int k = 0; k < 4; k++) {
                                    outv[k][0] = fmaf(g0, vB[k], outv[k][0]);
                                    outv[k][1] = fmaf(g1, vB[k], outv[k][1]);
                                    outv[k][2] = fmaf(g2, vB[k], outv[k][2]);
                                }
                            }
                        }
                    }
                }
                __syncwarp();
            }  // sweep

            if (pass == 0) {
                // in-warp softmax over 20 edges; coef folds 0.25 tp norm
                float L = -3.0e38f;
                if (lane < 20)
                    L = fmaf(0.022097086912079608f, ws[NS_LG + lane], ws[NS_LC + lane]);
                float M = L;
#pragma unroll
                for (int o = 16; o >= 1; o >>= 1)
                    M = fmaxf(M, __shfl_xor_sync(0xffffffffu, M, o));
                float ex = (lane < 20) ? __expf(L - M) : 0.f;
                float z = bsum(ex);
                if (lane < 20)
                    ws[NS_CO + lane] = 0.25f * sqrtf(__fdividef(ex, z) + 1e-12f);
                __syncwarp();
            }
        }  // active
    }  // pass

    // ---- warp output reduction: xor16 merges path pairs, xor8/4/2 sum over ii ----
    if (active) {
#pragma unroll
        for (int o = 16; o >= 2; o >>= 1) {
#pragma unroll
            for (int k = 0; k < 4; k++) {
                outs[k] += __shfl_xor_sync(0xffffffffu, outs[k], o);
#pragma unroll
                for (int c = 0; c < 3; c++)
                    outv[k][c] += __shfl_xor_sync(0xffffffffu, outv[k][c], o);
            }
        }
        if (lane < 2) {
            int o0 = lane * 4;
#pragma unroll
            for (int k = 0; k < 4; k++) {
                out[n * 32 + o0 + k] = outs[k];
#pragma unroll
                for (int c = 0; c < 3; c++)
                    out[n * 32 + 8 + (o0 + k) * 3 + c] = outv[k][c];
            }
        }
    }
}

extern "C" void kernel_launch(void* const* d_in, const int* in_sizes, int n_in,
                              void* d_out, int out_size) {
    const float* f    = (const float*)d_in[0];
    const float* pos  = (const float*)d_in[1];
    const float* Wq_s = (const float*)d_in[2];
    const float* Wq_v = (const float*)d_in[3];
    const float* Wk1  = (const float*)d_in[4];
    const float* Wk2  = (const float*)d_in[5];
    const float* Wv1  = (const float*)d_in[6];
    const float* Wv2  = (const float*)d_in[7];
    const float* Wd_s = (const float*)d_in[8];
    const float* Wd_v = (const float*)d_in[9];
    const int* esrc   = (const int*)d_in[10];
    float* out = (float*)d_out;

    cudaFuncSetAttribute(se3_main, cudaFuncAttributeMaxDynamicSharedMemorySize, SMEM_BYTES);
    k0_qt<<<64, 256>>>(f, Wq_s, Wq_v, Wd_s, Wd_v);
    se3_main<<<(NN + 11) / 12, 384, SMEM_BYTES>>>(f, pos, Wk1, Wk2, Wv1, Wv2, esrc, out);
}